// round 10
// baseline (speedup 1.0000x reference)
#include <cuda_runtime.h>
#include <cuda_fp16.h>
#include <math.h>
#include <stdint.h>

#define B_    2
#define S_    2048
#define HID_  4096
#define NH_   32
#define NKV_  8
#define HD_   128
#define SCALE_ 0.08838834764831845f   // 128^-0.5

// ======================= PTX helpers ========================================
__device__ __forceinline__ uint32_t smem_u32(const void* p) {
    uint32_t a;
    asm("{ .reg .u64 t; cvta.to.shared.u64 t, %1; cvt.u32.u64 %0, t; }"
        : "=r"(a) : "l"(p));
    return a;
}
#define CP_ASYNC16(dst, src) \
    asm volatile("cp.async.cg.shared.global [%0], [%1], 16;" :: "r"(dst), "l"(src))
#define CP_COMMIT() asm volatile("cp.async.commit_group;" ::: "memory")
#define CP_WAIT(n)  asm volatile("cp.async.wait_group %0;" :: "n"(n) : "memory")

#define LDSM4(r0, r1, r2, r3, a)                                              \
    asm volatile("ldmatrix.sync.aligned.m8n8.x4.shared.b16 {%0,%1,%2,%3}, [%4];" \
        : "=r"(r0), "=r"(r1), "=r"(r2), "=r"(r3) : "r"(a))
#define LDSM4T(r0, r1, r2, r3, a)                                             \
    asm volatile("ldmatrix.sync.aligned.m8n8.x4.trans.shared.b16 {%0,%1,%2,%3}, [%4];" \
        : "=r"(r0), "=r"(r1), "=r"(r2), "=r"(r3) : "r"(a))

#define MMA16816(c, av, bv)                                                   \
    asm volatile("mma.sync.aligned.m16n8k16.row.col.f32.f16.f16.f32 "         \
        "{%0,%1,%2,%3}, {%4,%5,%6,%7}, {%8,%9}, {%0,%1,%2,%3};"               \
        : "+f"((c)[0]), "+f"((c)[1]), "+f"((c)[2]), "+f"((c)[3])              \
        : "r"((av)[0]), "r"((av)[1]), "r"((av)[2]), "r"((av)[3]),             \
          "r"((bv)[0]), "r"((bv)[1]))

// ======================= scratch ============================================
__device__ __half g_hs_h[4096 * 4096], g_hs_l[4096 * 4096];
__device__ __half g_wq_h[4096 * 4096], g_wq_l[4096 * 4096];
__device__ __half g_wk_h[1024 * 4096], g_wk_l[1024 * 4096];
__device__ __half g_wv_h[1024 * 4096], g_wv_l[1024 * 4096];
__device__ __half g_wo_h[4096 * 4096], g_wo_l[4096 * 4096];
__device__ __half g_o_h [4096 * 4096], g_o_l [4096 * 4096];
// projection outputs (Q/K already rope'd), head layout [B,H,S,HD]
__device__ __half g_qh [B_ * NH_  * S_ * HD_], g_ql [B_ * NH_  * S_ * HD_];
__device__ __half g_kh [B_ * NKV_ * S_ * HD_], g_kl [B_ * NKV_ * S_ * HD_];
__device__ __half g_vh [B_ * NKV_ * S_ * HD_], g_vl [B_ * NKV_ * S_ * HD_];

// ======================= split fp32 -> fp16 hi/lo ============================
__global__ void __launch_bounds__(256)
split_hilo(const float* __restrict__ x, __half* __restrict__ hi,
           __half* __restrict__ lo, int n4)
{
    int i = blockIdx.x * blockDim.x + threadIdx.x;
    if (i >= n4) return;
    float4 v = ((const float4*)x)[i];
    __half h0 = __float2half(v.x), h1 = __float2half(v.y);
    __half h2 = __float2half(v.z), h3 = __float2half(v.w);
    __half l0 = __float2half(v.x - __half2float(h0));
    __half l1 = __float2half(v.y - __half2float(h1));
    __half l2 = __float2half(v.z - __half2float(h2));
    __half l3 = __float2half(v.w - __half2float(h3));
    ((__half2*)hi)[2 * i + 0] = __halves2half2(h0, h1);
    ((__half2*)hi)[2 * i + 1] = __halves2half2(h2, h3);
    ((__half2*)lo)[2 * i + 0] = __halves2half2(l0, l1);
    ((__half2*)lo)[2 * i + 1] = __halves2half2(l2, l3);
}

// ======================= HMMA fp16x3 GEMM ====================================
// CTA 256x128, 8 warps (4m x 2n), warp tile 64x64, K-tile 64, double buffer.
// MODE 0: C fp32 flat [M, Ntot]
// MODE 2: fused QKV — B select by blockIdx.x; epilogue stages tile in smem,
//         applies RoPE to Q/K, writes hi/lo fp16 in head layout.
#define ROWB  144                     // 72 halfs row stride (64 data + 8 pad)
#define ATILEB (256 * ROWB)           // 36864 B
#define BTILEB (128 * ROWB)           // 18432 B
#define STAGEB (2 * ATILEB + 2 * BTILEB) // 110592 B
#define GSMEM_BYTES (2 * STAGEB)      // 221184 B
#define EPI_STRIDE 132                // fp32 epilogue tile stride (floats)

template <int MODE>
__global__ void __launch_bounds__(256)
gemm3_h16(const __half* __restrict__ Ah, const __half* __restrict__ Al,
          const __half* __restrict__ Bqh, const __half* __restrict__ Bql,
          const __half* __restrict__ Bkh, const __half* __restrict__ Bkl,
          const __half* __restrict__ Bvh, const __half* __restrict__ Bvl,
          const float* __restrict__ Cs, const float* __restrict__ Sn,
          float* __restrict__ C, int K, int Ntot,
          __half* __restrict__ Qh, __half* __restrict__ Ql,
          __half* __restrict__ Kh, __half* __restrict__ Kl,
          __half* __restrict__ Vh, __half* __restrict__ Vl)
{
    extern __shared__ char smem[];
    const uint32_t sbase = smem_u32(smem);
    const int tid  = threadIdx.x;
    const int wid  = tid >> 5;
    const int lane = tid & 31;
    const int bx = blockIdx.x;
    const int m0 = blockIdx.y * 256;
    const int wm0 = (wid & 3) * 64;
    const int wn0 = (wid >> 2) * 64;
    const int niter = K >> 6;

    const __half *Bh_, *Bl_;
    int n0;
    if (MODE == 2) {
        if (bx < 32)      { Bh_ = Bqh; Bl_ = Bql; n0 = bx * 128; }
        else if (bx < 40) { Bh_ = Bkh; Bl_ = Bkl; n0 = (bx - 32) * 128; }
        else              { Bh_ = Bvh; Bl_ = Bvl; n0 = (bx - 40) * 128; }
    } else {
        Bh_ = Bqh; Bl_ = Bql; n0 = bx * 128;
    }

    float acc[4][8][4];
#pragma unroll
    for (int i = 0; i < 4; i++)
#pragma unroll
        for (int j = 0; j < 8; j++)
#pragma unroll
            for (int r = 0; r < 4; r++) acc[i][j][r] = 0.0f;

    auto load_stage = [&](int it, int st) {
        uint32_t base = sbase + st * STAGEB;
        int kt = it << 6;
#pragma unroll
        for (int u = 0; u < 8; u++) {
            int c = tid + u * 256;
            int row = c >> 3, seg = c & 7;
            uint32_t o = (uint32_t)row * ROWB + seg * 16;
            size_t go = (size_t)(m0 + row) * K + kt + seg * 8;
            CP_ASYNC16(base + o,          Ah + go);
            CP_ASYNC16(base + ATILEB + o, Al + go);
        }
#pragma unroll
        for (int u = 0; u < 4; u++) {
            int c = tid + u * 256;
            int row = c >> 3, seg = c & 7;
            uint32_t o = (uint32_t)row * ROWB + seg * 16;
            size_t go = (size_t)(n0 + row) * K + kt + seg * 8;
            CP_ASYNC16(base + 2 * ATILEB + o,          Bh_ + go);
            CP_ASYNC16(base + 2 * ATILEB + BTILEB + o, Bl_ + go);
        }
        CP_COMMIT();
    };

    const uint32_t a_off = (uint32_t)(wm0 + (lane & 15)) * ROWB + (lane >> 4) * 16;
    const uint32_t b_off = (uint32_t)(wn0 + ((lane >> 4) & 1) * 8 + (lane & 7)) * ROWB
                         + ((lane >> 3) & 1) * 16;

    load_stage(0, 0);
    for (int it = 0; it < niter; it++) {
        if (it + 1 < niter) { load_stage(it + 1, (it + 1) & 1); CP_WAIT(1); }
        else                { CP_WAIT(0); }
        __syncthreads();

        uint32_t tb = sbase + (it & 1) * STAGEB;
        uint32_t As_h = tb, As_l = tb + ATILEB;
        uint32_t Bs_h = tb + 2 * ATILEB, Bs_l = tb + 2 * ATILEB + BTILEB;

#pragma unroll
        for (int k16 = 0; k16 < 4; k16++) {
            uint32_t kb = k16 * 32;
            uint32_t ah[4][4], al[4][4];
#pragma unroll
            for (int mt = 0; mt < 4; mt++) {
                uint32_t o = a_off + mt * 16 * ROWB + kb;
                LDSM4(ah[mt][0], ah[mt][1], ah[mt][2], ah[mt][3], As_h + o);
                LDSM4(al[mt][0], al[mt][1], al[mt][2], al[mt][3], As_l + o);
            }
#pragma unroll
            for (int np = 0; np < 4; np++) {
                uint32_t o = b_off + np * 16 * ROWB + kb;
                uint32_t bh[4], bl[4];
                LDSM4(bh[0], bh[1], bh[2], bh[3], Bs_h + o);
                LDSM4(bl[0], bl[1], bl[2], bl[3], Bs_l + o);
#pragma unroll
                for (int mt = 0; mt < 4; mt++) {
                    MMA16816(acc[mt][2*np],   ah[mt], bh);
                    MMA16816(acc[mt][2*np],   ah[mt], bl);
                    MMA16816(acc[mt][2*np],   al[mt], bh);
                    MMA16816(acc[mt][2*np+1], ah[mt], bh + 2);
                    MMA16816(acc[mt][2*np+1], ah[mt], bl + 2);
                    MMA16816(acc[mt][2*np+1], al[mt], bh + 2);
                }
            }
        }
        __syncthreads();
    }

    if (MODE == 2) {
        // stage fp32 tile into smem (reuse stage buffers), then rope + split
        float* ft = (float*)smem;
#pragma unroll
        for (int mt = 0; mt < 4; mt++) {
            int r = wm0 + mt * 16 + (lane >> 2);
#pragma unroll
            for (int nt = 0; nt < 8; nt++) {
                int cl = wn0 + nt * 8 + (lane & 3) * 2;
                *(float2*)&ft[(size_t)r * EPI_STRIDE + cl] =
                    make_float2(acc[mt][nt][0], acc[mt][nt][1]);
                *(float2*)&ft[(size_t)(r + 8) * EPI_STRIDE + cl] =
                    make_float2(acc[mt][nt][2], acc[mt][nt][3]);
            }
        }
        __syncthreads();

        __half *Oh_, *Ol_; int Hh, hh;
        bool rope;
        if (bx < 32)      { hh = bx;      Oh_ = Qh; Ol_ = Ql; Hh = NH_;  rope = true; }
        else if (bx < 40) { hh = bx - 32; Oh_ = Kh; Ol_ = Kl; Hh = NKV_; rope = true; }
        else              { hh = bx - 40; Oh_ = Vh; Ol_ = Vl; Hh = NKV_; rope = false; }

        const int row = tid;                  // 0..255
        const int m = m0 + row;
        const int b = m >> 11;
        const int s = m & (S_ - 1);
        const size_t ob = (((size_t)(b * Hh + hh)) * S_ + s) * HD_;
        const size_t ci = ((size_t)(b * S_ + s)) * HD_;
        const float* fr = ft + (size_t)row * EPI_STRIDE;

        if (rope) {
#pragma unroll
            for (int c4 = 0; c4 < 16; c4++) {
                int da = c4 * 4, db = da + 64;
                float4 xa = *(const float4*)&fr[da];
                float4 xb = *(const float4*)&fr[db];
                float4 ca = *(const float4*)&Cs[ci + da];
                float4 cb = *(const float4*)&Cs[ci + db];
                float4 sa = *(const float4*)&Sn[ci + da];
                float4 sb = *(const float4*)&Sn[ci + db];
                float4 oa = make_float4(xa.x * ca.x - xb.x * sa.x,
                                        xa.y * ca.y - xb.y * sa.y,
                                        xa.z * ca.z - xb.z * sa.z,
                                        xa.w * ca.w - xb.w * sa.w);
                float4 obv = make_float4(xb.x * cb.x + xa.x * sb.x,
                                         xb.y * cb.y + xa.y * sb.y,
                                         xb.z * cb.z + xa.z * sb.z,
                                         xb.w * cb.w + xa.w * sb.w);
                __half2 ha0 = __floats2half2_rn(oa.x, oa.y);
                __half2 ha1 = __floats2half2_rn(oa.z, oa.w);
                __half2 la0 = __floats2half2_rn(oa.x - __low2float(ha0),
                                                oa.y - __high2float(ha0));
                __half2 la1 = __floats2half2_rn(oa.z - __low2float(ha1),
                                                oa.w - __high2float(ha1));
                *(__half2*)&Oh_[ob + da]     = ha0;
                *(__half2*)&Oh_[ob + da + 2] = ha1;
                *(__half2*)&Ol_[ob + da]     = la0;
                *(__half2*)&Ol_[ob + da + 2] = la1;
                __half2 hb0 = __floats2half2_rn(obv.x, obv.y);
                __half2 hb1 = __floats2half2_rn(obv.z, obv.w);
                __half2 lb0 = __floats2half2_rn(obv.x - __low2float(hb0),
                                                obv.y - __high2float(hb0));
                __half2 lb1 = __floats2half2_rn(obv.z - __low2float(hb1),
                                                obv.w - __high2float(hb1));
                *(__half2*)&Oh_[ob + db]     = hb0;
                *(__half2*)&Oh_[ob + db + 2] = hb1;
                *(__half2*)&Ol_[ob + db]     = lb0;
                *(__half2*)&Ol_[ob + db + 2] = lb1;
            }
        } else {
#pragma unroll
            for (int c4 = 0; c4 < 32; c4++) {
                int d = c4 * 4;
                float4 x = *(const float4*)&fr[d];
                __half2 h0 = __floats2half2_rn(x.x, x.y);
                __half2 h1 = __floats2half2_rn(x.z, x.w);
                __half2 l0 = __floats2half2_rn(x.x - __low2float(h0),
                                               x.y - __high2float(h0));
                __half2 l1 = __floats2half2_rn(x.z - __low2float(h1),
                                               x.w - __high2float(h1));
                *(__half2*)&Oh_[ob + d]     = h0;
                *(__half2*)&Oh_[ob + d + 2] = h1;
                *(__half2*)&Ol_[ob + d]     = l0;
                *(__half2*)&Ol_[ob + d + 2] = l1;
            }
        }
    } else {
#pragma unroll
        for (int mt = 0; mt < 4; mt++) {
            int r = m0 + wm0 + mt * 16 + (lane >> 2);
#pragma unroll
            for (int nt = 0; nt < 8; nt++) {
                int cl = bx * 128 + wn0 + nt * 8 + (lane & 3) * 2;
                float* p0 = C + (size_t)r * Ntot + cl;
                *(float2*)p0 = make_float2(acc[mt][nt][0], acc[mt][nt][1]);
                float* p1 = C + (size_t)(r + 8) * Ntot + cl;
                *(float2*)p1 = make_float2(acc[mt][nt][2], acc[mt][nt][3]);
            }
        }
    }
}

// ======================= HMMA flash attention (R8 version) ===================
// BQ=128 (8 warps x 16 rows), BK=64, fp16 x3 split, fp32 accum, causal.
#define FROWB 272
#define FTILE (64 * FROWB)
#define QTILE (128 * FROWB)
#define FSMEM_BYTES (2 * QTILE + 8 * FTILE)

__global__ void __launch_bounds__(256)
flash16(const __half* __restrict__ Qh, const __half* __restrict__ Ql,
        const __half* __restrict__ Kh, const __half* __restrict__ Kl,
        const __half* __restrict__ Vh, const __half* __restrict__ Vl,
        __half* __restrict__ Oh, __half* __restrict__ Ol)
{
    extern __shared__ char smc[];
    const uint32_t sb = smem_u32(smc);
    const int qt = blockIdx.x, h = blockIdx.y, b = blockIdx.z;
    const int kvh = h >> 2;
    const int tid = threadIdx.x, wid = tid >> 5, lane = tid & 31;
    const int q0 = qt * 128;
    const int tmax = 2 * qt + 1;
    const size_t qg  = ((size_t)(b * NH_ + h) * S_ + q0) * HD_;
    const size_t kvg = ((size_t)(b * NKV_ + kvh) * S_) * HD_;

#pragma unroll
    for (int u = 0; u < 16; u++) {
        int c = tid + u * 256;
        int comp = c >> 11, r = (c >> 4) & 127, ch = c & 15;
        const __half* src = (comp ? Ql : Qh) + qg + (size_t)r * HD_ + ch * 8;
        CP_ASYNC16(sb + comp * QTILE + r * FROWB + ch * 16, src);
    }
    auto load_kv = [&](int t, int st) {
        uint32_t base = sb + 2 * QTILE + st * 4 * FTILE;
        size_t g = kvg + (size_t)t * 64 * HD_;
#pragma unroll
        for (int u = 0; u < 16; u++) {
            int c = tid + u * 256;
            int comp = c >> 10, r = (c >> 4) & 63, ch = c & 15;
            const __half* src = (comp == 0 ? Kh : comp == 1 ? Kl
                               : comp == 2 ? Vh : Vl) + g + (size_t)r * HD_ + ch * 8;
            CP_ASYNC16(base + comp * FTILE + r * FROWB + ch * 16, src);
        }
        CP_COMMIT();
    };
    load_kv(0, 0);
    load_kv(1, 1);

    float oacc[16][4];
#pragma unroll
    for (int i = 0; i < 16; i++)
#pragma unroll
        for (int r = 0; r < 4; r++) oacc[i][r] = 0.0f;
    float mrun0 = -1e30f, mrun1 = -1e30f, lrun0 = 0.0f, lrun1 = 0.0f;

    const uint32_t qa_off = (uint32_t)(wid * 16 + (lane & 15)) * FROWB + (lane >> 4) * 16;
    const uint32_t ka_off = (uint32_t)(((lane >> 4) & 1) * 8 + (lane & 7)) * FROWB
                          + ((lane >> 3) & 1) * 16;
    const uint32_t va_off = (uint32_t)(lane & 15) * FROWB + ((lane >> 4) & 1) * 16;

    for (int t = 0; t <= tmax; t++) {
        if (t < tmax) { CP_WAIT(1); } else { CP_WAIT(0); }
        __syncthreads();
        uint32_t kb = sb + 2 * QTILE + (t & 1) * 4 * FTILE;
        uint32_t Khs = kb, Kls = kb + FTILE, Vhs = kb + 2 * FTILE, Vls = kb + 3 * FTILE;

        float sacc[8][4];
#pragma unroll
        for (int i = 0; i < 8; i++)
#pragma unroll
            for (int r = 0; r < 4; r++) sacc[i][r] = 0.0f;

#pragma unroll
        for (int j = 0; j < 8; j++) {
            uint32_t qo = qa_off + j * 32;
            uint32_t qhf[4], qlf[4];
            LDSM4(qhf[0], qhf[1], qhf[2], qhf[3], sb + qo);
            LDSM4(qlf[0], qlf[1], qlf[2], qlf[3], sb + QTILE + qo);
#pragma unroll
            for (int p = 0; p < 4; p++) {
                uint32_t ko = ka_off + p * 16 * FROWB + j * 32;
                uint32_t khf[4], klf[4];
                LDSM4(khf[0], khf[1], khf[2], khf[3], Khs + ko);
                LDSM4(klf[0], klf[1], klf[2], klf[3], Kls + ko);
                MMA16816(sacc[2*p],   qhf, khf);
                MMA16816(sacc[2*p],   qhf, klf);
                MMA16816(sacc[2*p],   qlf, khf);
                MMA16816(sacc[2*p+1], qhf, khf + 2);
                MMA16816(sacc[2*p+1], qhf, klf + 2);
                MMA16816(sacc[2*p+1], qlf, khf + 2);
            }
        }

#pragma unroll
        for (int j = 0; j < 8; j++)
#pragma unroll
            for (int r = 0; r < 4; r++) sacc[j][r] *= SCALE_;

        if (t >= 2 * qt) {
            int rg = q0 + wid * 16 + (lane >> 2);
#pragma unroll
            for (int j = 0; j < 8; j++) {
                int cg = 64 * t + 8 * j + (lane & 3) * 2;
                if (cg     > rg)     sacc[j][0] = -1e30f;
                if (cg + 1 > rg)     sacc[j][1] = -1e30f;
                if (cg     > rg + 8) sacc[j][2] = -1e30f;
                if (cg + 1 > rg + 8) sacc[j][3] = -1e30f;
            }
        }
        float mx0 = -1e30f, mx1 = -1e30f;
#pragma unroll
        for (int j = 0; j < 8; j++) {
            mx0 = fmaxf(mx0, fmaxf(sacc[j][0], sacc[j][1]));
            mx1 = fmaxf(mx1, fmaxf(sacc[j][2], sacc[j][3]));
        }
        mx0 = fmaxf(mx0, __shfl_xor_sync(0xffffffffu, mx0, 1));
        mx0 = fmaxf(mx0, __shfl_xor_sync(0xffffffffu, mx0, 2));
        mx1 = fmaxf(mx1, __shfl_xor_sync(0xffffffffu, mx1, 1));
        mx1 = fmaxf(mx1, __shfl_xor_sync(0xffffffffu, mx1, 2));
        float mn0 = fmaxf(mrun0, mx0), mn1 = fmaxf(mrun1, mx1);
        float al0 = __expf(mrun0 - mn0), al1 = __expf(mrun1 - mn1);

        uint32_t ph[8][2], pl[8][2];
        float l0 = 0.0f, l1 = 0.0f;
#pragma unroll
        for (int j = 0; j < 8; j++) {
            float p0 = __expf(sacc[j][0] - mn0), p1 = __expf(sacc[j][1] - mn0);
            float p2 = __expf(sacc[j][2] - mn1), p3 = __expf(sacc[j][3] - mn1);
            l0 += p0 + p1; l1 += p2 + p3;
            __half2 h01 = __floats2half2_rn(p0, p1);
            __half2 h23 = __floats2half2_rn(p2, p3);
            ph[j][0] = *(uint32_t*)&h01;
            ph[j][1] = *(uint32_t*)&h23;
            __half2 r01 = __floats2half2_rn(p0 - __low2float(h01), p1 - __high2float(h01));
            __half2 r23 = __floats2half2_rn(p2 - __low2float(h23), p3 - __high2float(h23));
            pl[j][0] = *(uint32_t*)&r01;
            pl[j][1] = *(uint32_t*)&r23;
        }
        l0 += __shfl_xor_sync(0xffffffffu, l0, 1);
        l0 += __shfl_xor_sync(0xffffffffu, l0, 2);
        l1 += __shfl_xor_sync(0xffffffffu, l1, 1);
        l1 += __shfl_xor_sync(0xffffffffu, l1, 2);
        lrun0 = lrun0 * al0 + l0; lrun1 = lrun1 * al1 + l1;
        mrun0 = mn0; mrun1 = mn1;
#pragma unroll
        for (int nt = 0; nt < 16; nt++) {
            oacc[nt][0] *= al0; oacc[nt][1] *= al0;
            oacc[nt][2] *= al1; oacc[nt][3] *= al1;
        }

#pragma unroll
        for (int jc = 0; jc < 4; jc++) {
            uint32_t pfh[4] = {ph[2*jc][0], ph[2*jc][1], ph[2*jc+1][0], ph[2*jc+1][1]};
            uint32_t pfl[4] = {pl[2*jc][0], pl[2*jc][1], pl[2*jc+1][0], pl[2*jc+1][1]};
#pragma unroll
            for (int dp = 0; dp < 8; dp++) {
                uint32_t vo = va_off + jc * 16 * FROWB + dp * 32;
                uint32_t vhf[4], vlf[4];
                LDSM4T(vhf[0], vhf[1], vhf[2], vhf[3], Vhs + vo);
                LDSM4T(vlf[0], vlf[1], vlf[2], vlf[3], Vls + vo);
                MMA16816(oacc[2*dp],   pfh, vhf);
                MMA16816(oacc[2*dp],   pfh, vlf);
                MMA16816(oacc[2*dp],   pfl, vhf);
                MMA16816(oacc[2*dp+1], pfh, vhf + 2);
                MMA16816(oacc[2*dp+1], pfh, vlf + 2);
                MMA16816(oacc[2*dp+1], pfl, vhf + 2);
            }
        }
        __syncthreads();
        if (t + 2 <= tmax) load_kv(t + 2, t & 1);
    }

    float inv0 = 1.0f / lrun0, inv1 = 1.0f / lrun1;
    int r0 = q0 + wid * 16 + (lane >> 2);
    size_t ob0 = ((size_t)(b * S_ + r0)) * (NH_ * HD_) + h * HD_;
    size_t ob1 = ((size_t)(b * S_ + r0 + 8)) * (NH_ * HD_) + h * HD_;
#pragma unroll
    for (int nt = 0; nt < 16; nt++) {
        int col = nt * 8 + (lane & 3) * 2;
        float f0 = oacc[nt][0] * inv0, f1 = oacc[nt][1] * inv0;
        float f2 = oacc[nt][2] * inv1, f3 = oacc[nt][3] * inv1;
        __half2 h01 = __floats2half2_rn(f0, f1);
        __half2 h23 = __floats2half2_rn(f2, f3);
        __half2 l01 = __floats2half2_rn(f0 - __low2float(h01), f1 - __high2float(h01));
        __half2 l23 = __floats2half2_rn(f2 - __low2float(h23), f3 - __high2float(h23));
        *(__half2*)&Oh[ob0 + col] = h01;
        *(__half2*)&Ol[ob0 + col] = l01;
        *(__half2*)&Oh[ob1 + col] = h23;
        *(__half2*)&Ol[ob1 + col] = l23;
    }
}

// ======================= launch ==============================================
extern "C" void kernel_launch(void* const* d_in, const int* in_sizes, int n_in,
                              void* d_out, int out_size)
{
    (void)in_sizes; (void)n_in; (void)out_size;
    const float* hs = (const float*)d_in[0];
    const float* cs = (const float*)d_in[1];
    const float* sn = (const float*)d_in[2];
    const float* Wq = (const float*)d_in[4];
    const float* Wk = (const float*)d_in[5];
    const float* Wv = (const float*)d_in[6];
    const float* Wo = (const float*)d_in[7];
    float* out = (float*)d_out;

    __half *hsh, *hsl, *wqh, *wql, *wkh, *wkl, *wvh, *wvl, *woh, *wol, *oh, *ol;
    __half *qh, *ql, *kh, *kl, *vh, *vl;
    cudaGetSymbolAddress((void**)&hsh, g_hs_h); cudaGetSymbolAddress((void**)&hsl, g_hs_l);
    cudaGetSymbolAddress((void**)&wqh, g_wq_h); cudaGetSymbolAddress((void**)&wql, g_wq_l);
    cudaGetSymbolAddress((void**)&wkh, g_wk_h); cudaGetSymbolAddress((void**)&wkl, g_wk_l);
    cudaGetSymbolAddress((void**)&wvh, g_wv_h); cudaGetSymbolAddress((void**)&wvl, g_wv_l);
    cudaGetSymbolAddress((void**)&woh, g_wo_h); cudaGetSymbolAddress((void**)&wol, g_wo_l);
    cudaGetSymbolAddress((void**)&oh,  g_o_h);  cudaGetSymbolAddress((void**)&ol,  g_o_l);
    cudaGetSymbolAddress((void**)&qh,  g_qh);   cudaGetSymbolAddress((void**)&ql,  g_ql);
    cudaGetSymbolAddress((void**)&kh,  g_kh);   cudaGetSymbolAddress((void**)&kl,  g_kl);
    cudaGetSymbolAddress((void**)&vh,  g_vh);   cudaGetSymbolAddress((void**)&vl,  g_vl);

    const int n_big = 4096 * 4096 / 4, n_sm = 1024 * 4096 / 4;
    split_hilo<<<(n_big + 255) / 256, 256>>>(hs, hsh, hsl, n_big);
    split_hilo<<<(n_big + 255) / 256, 256>>>(Wq, wqh, wql, n_big);
    split_hilo<<<(n_sm + 255) / 256, 256>>>(Wk, wkh, wkl, n_sm);
    split_hilo<<<(n_sm + 255) / 256, 256>>>(Wv, wvh, wvl, n_sm);
    split_hilo<<<(n_big + 255) / 256, 256>>>(Wo, woh, wol, n_big);

    cudaFuncSetAttribute(gemm3_h16<0>,
                         cudaFuncAttributeMaxDynamicSharedMemorySize, GSMEM_BYTES);
    cudaFuncSetAttribute(gemm3_h16<2>,
                         cudaFuncAttributeMaxDynamicSharedMemorySize, GSMEM_BYTES);

    // fused QKV projection + RoPE epilogue
    gemm3_h16<2><<<dim3(48, 16), 256, GSMEM_BYTES>>>(
        hsh, hsl, wqh, wql, wkh, wkl, wvh, wvl, cs, sn,
        nullptr, 4096, 0, qh, ql, kh, kl, vh, vl);

    cudaFuncSetAttribute(flash16,
                         cudaFuncAttributeMaxDynamicSharedMemorySize, FSMEM_BYTES);
    flash16<<<dim3(S_ / 128, NH_, B_), 256, FSMEM_BYTES>>>(
        qh, ql, kh, kl, vh, vl, oh, ol);

    // output projection: fp32 flat out
    gemm3_h16<0><<<dim3(32, 16), 256, GSMEM_BYTES>>>(
        oh, ol, woh, wol, nullptr, nullptr, nullptr, nullptr, nullptr, nullptr,
        out, 4096, 4096, nullptr, nullptr, nullptr, nullptr, nullptr, nullptr);
}

// round 14
// speedup vs baseline: 1.0239x; 1.0239x over previous
#include <cuda_runtime.h>
#include <cuda_fp16.h>
#include <math.h>
#include <stdint.h>

#define B_    2
#define S_    2048
#define HID_  4096
#define NH_   32
#define NKV_  8
#define HD_   128
#define SCALE_ 0.08838834764831845f   // 128^-0.5

// ======================= PTX helpers ========================================
__device__ __forceinline__ uint32_t smem_u32(const void* p) {
    uint32_t a;
    asm("{ .reg .u64 t; cvta.to.shared.u64 t, %1; cvt.u32.u64 %0, t; }"
        : "=r"(a) : "l"(p));
    return a;
}
#define CP_ASYNC16(dst, src) \
    asm volatile("cp.async.cg.shared.global [%0], [%1], 16;" :: "r"(dst), "l"(src))
#define CP_COMMIT() asm volatile("cp.async.commit_group;" ::: "memory")
#define CP_WAIT(n)  asm volatile("cp.async.wait_group %0;" :: "n"(n) : "memory")

#define LDSM4(r0, r1, r2, r3, a)                                              \
    asm volatile("ldmatrix.sync.aligned.m8n8.x4.shared.b16 {%0,%1,%2,%3}, [%4];" \
        : "=r"(r0), "=r"(r1), "=r"(r2), "=r"(r3) : "r"(a))
#define LDSM4T(r0, r1, r2, r3, a)                                             \
    asm volatile("ldmatrix.sync.aligned.m8n8.x4.trans.shared.b16 {%0,%1,%2,%3}, [%4];" \
        : "=r"(r0), "=r"(r1), "=r"(r2), "=r"(r3) : "r"(a))

#define MMA16816(c, av, bv)                                                   \
    asm volatile("mma.sync.aligned.m16n8k16.row.col.f32.f16.f16.f32 "         \
        "{%0,%1,%2,%3}, {%4,%5,%6,%7}, {%8,%9}, {%0,%1,%2,%3};"               \
        : "+f"((c)[0]), "+f"((c)[1]), "+f"((c)[2]), "+f"((c)[3])              \
        : "r"((av)[0]), "r"((av)[1]), "r"((av)[2]), "r"((av)[3]),             \
          "r"((bv)[0]), "r"((bv)[1]))

// ======================= scratch ============================================
__device__ __half g_hs_h[4096 * 4096], g_hs_l[4096 * 4096];
__device__ __half g_wq_h[4096 * 4096], g_wq_l[4096 * 4096];
__device__ __half g_wk_h[1024 * 4096], g_wk_l[1024 * 4096];
__device__ __half g_wv_h[1024 * 4096], g_wv_l[1024 * 4096];
__device__ __half g_wo_h[4096 * 4096], g_wo_l[4096 * 4096];
__device__ __half g_o_h [4096 * 4096], g_o_l [4096 * 4096];
// projection outputs (pre-rope), head layout [B,H,S,HD]
__device__ __half g_qh [B_ * NH_  * S_ * HD_], g_ql [B_ * NH_  * S_ * HD_];
__device__ __half g_kh [B_ * NKV_ * S_ * HD_], g_kl [B_ * NKV_ * S_ * HD_];
__device__ __half g_vh [B_ * NKV_ * S_ * HD_], g_vl [B_ * NKV_ * S_ * HD_];
// rope'd
__device__ __half g_qrh[B_ * NH_  * S_ * HD_], g_qrl[B_ * NH_  * S_ * HD_];
__device__ __half g_krh[B_ * NKV_ * S_ * HD_], g_krl[B_ * NKV_ * S_ * HD_];

// ======================= split fp32 -> fp16 hi/lo ============================
__global__ void __launch_bounds__(256)
split_hilo(const float* __restrict__ x, __half* __restrict__ hi,
           __half* __restrict__ lo, int n4)
{
    int i = blockIdx.x * blockDim.x + threadIdx.x;
    if (i >= n4) return;
    float4 v = ((const float4*)x)[i];
    __half h0 = __float2half(v.x), h1 = __float2half(v.y);
    __half h2 = __float2half(v.z), h3 = __float2half(v.w);
    __half l0 = __float2half(v.x - __half2float(h0));
    __half l1 = __float2half(v.y - __half2float(h1));
    __half l2 = __float2half(v.z - __half2float(h2));
    __half l3 = __float2half(v.w - __half2float(h3));
    ((__half2*)hi)[2 * i + 0] = __halves2half2(h0, h1);
    ((__half2*)hi)[2 * i + 1] = __halves2half2(h2, h3);
    ((__half2*)lo)[2 * i + 0] = __halves2half2(l0, l1);
    ((__half2*)lo)[2 * i + 1] = __halves2half2(l2, l3);
}

// ======================= HMMA fp16x3 GEMM ====================================
// CTA 256x128, 8 warps (4m x 2n), warp tile 64x64, K-tile 64, double buffer.
// MODE 0: C fp32 flat [M, Ntot]
// MODE 2: fused QKV — per-blockIdx.x B select, hi/lo fp16 out in head layout
#define ROWB  144                     // 72 halfs row stride (64 data + 8 pad)
#define ATILEB (256 * ROWB)           // 36864 B
#define BTILEB (128 * ROWB)           // 18432 B
#define STAGEB (2 * ATILEB + 2 * BTILEB) // 110592 B
#define GSMEM_BYTES (2 * STAGEB)      // 221184 B

template <int MODE>
__global__ void __launch_bounds__(256)
gemm3_h16(const __half* __restrict__ Ah, const __half* __restrict__ Al,
          const __half* __restrict__ Bqh, const __half* __restrict__ Bql,
          const __half* __restrict__ Bkh, const __half* __restrict__ Bkl,
          const __half* __restrict__ Bvh, const __half* __restrict__ Bvl,
          float* __restrict__ C, int K, int Ntot,
          __half* __restrict__ Qh, __half* __restrict__ Ql,
          __half* __restrict__ Kh, __half* __restrict__ Kl,
          __half* __restrict__ Vh, __half* __restrict__ Vl)
{
    extern __shared__ char smem[];
    const uint32_t sbase = smem_u32(smem);
    const int tid  = threadIdx.x;
    const int wid  = tid >> 5;
    const int lane = tid & 31;
    const int bx = blockIdx.x;
    const int m0 = blockIdx.y * 256;
    const int wm0 = (wid & 3) * 64;
    const int wn0 = (wid >> 2) * 64;
    const int niter = K >> 6;

    // select B operand + output target
    const __half *Bh_, *Bl_;
    int n0;          // row offset into the selected B matrix
    if (MODE == 2) {
        if (bx < 32)      { Bh_ = Bqh; Bl_ = Bql; n0 = bx * 128; }
        else if (bx < 40) { Bh_ = Bkh; Bl_ = Bkl; n0 = (bx - 32) * 128; }
        else              { Bh_ = Bvh; Bl_ = Bvl; n0 = (bx - 40) * 128; }
    } else {
        Bh_ = Bqh; Bl_ = Bql; n0 = bx * 128;
    }

    float acc[4][8][4];
#pragma unroll
    for (int i = 0; i < 4; i++)
#pragma unroll
        for (int j = 0; j < 8; j++)
#pragma unroll
            for (int r = 0; r < 4; r++) acc[i][j][r] = 0.0f;

    auto load_stage = [&](int it, int st) {
        uint32_t base = sbase + st * STAGEB;
        int kt = it << 6;
#pragma unroll
        for (int u = 0; u < 8; u++) {
            int c = tid + u * 256;
            int row = c >> 3, seg = c & 7;
            uint32_t o = (uint32_t)row * ROWB + seg * 16;
            size_t go = (size_t)(m0 + row) * K + kt + seg * 8;
            CP_ASYNC16(base + o,          Ah + go);
            CP_ASYNC16(base + ATILEB + o, Al + go);
        }
#pragma unroll
        for (int u = 0; u < 4; u++) {
            int c = tid + u * 256;
            int row = c >> 3, seg = c & 7;
            uint32_t o = (uint32_t)row * ROWB + seg * 16;
            size_t go = (size_t)(n0 + row) * K + kt + seg * 8;
            CP_ASYNC16(base + 2 * ATILEB + o,          Bh_ + go);
            CP_ASYNC16(base + 2 * ATILEB + BTILEB + o, Bl_ + go);
        }
        CP_COMMIT();
    };

    const uint32_t a_off = (uint32_t)(wm0 + (lane & 15)) * ROWB + (lane >> 4) * 16;
    const uint32_t b_off = (uint32_t)(wn0 + ((lane >> 4) & 1) * 8 + (lane & 7)) * ROWB
                         + ((lane >> 3) & 1) * 16;

    load_stage(0, 0);
    for (int it = 0; it < niter; it++) {
        if (it + 1 < niter) { load_stage(it + 1, (it + 1) & 1); CP_WAIT(1); }
        else                { CP_WAIT(0); }
        __syncthreads();

        uint32_t tb = sbase + (it & 1) * STAGEB;
        uint32_t As_h = tb, As_l = tb + ATILEB;
        uint32_t Bs_h = tb + 2 * ATILEB, Bs_l = tb + 2 * ATILEB + BTILEB;

#pragma unroll
        for (int k16 = 0; k16 < 4; k16++) {
            uint32_t kb = k16 * 32;
            uint32_t ah[4][4], al[4][4];
#pragma unroll
            for (int mt = 0; mt < 4; mt++) {
                uint32_t o = a_off + mt * 16 * ROWB + kb;
                LDSM4(ah[mt][0], ah[mt][1], ah[mt][2], ah[mt][3], As_h + o);
                LDSM4(al[mt][0], al[mt][1], al[mt][2], al[mt][3], As_l + o);
            }
#pragma unroll
            for (int np = 0; np < 4; np++) {
                uint32_t o = b_off + np * 16 * ROWB + kb;
                uint32_t bh[4], bl[4];
                LDSM4(bh[0], bh[1], bh[2], bh[3], Bs_h + o);
                LDSM4(bl[0], bl[1], bl[2], bl[3], Bs_l + o);
#pragma unroll
                for (int mt = 0; mt < 4; mt++) {
                    MMA16816(acc[mt][2*np],   ah[mt], bh);
                    MMA16816(acc[mt][2*np],   ah[mt], bl);
                    MMA16816(acc[mt][2*np],   al[mt], bh);
                    MMA16816(acc[mt][2*np+1], ah[mt], bh + 2);
                    MMA16816(acc[mt][2*np+1], ah[mt], bl + 2);
                    MMA16816(acc[mt][2*np+1], al[mt], bh + 2);
                }
            }
        }
        __syncthreads();
    }

    if (MODE == 2) {
        // hi/lo fp16 out in head layout [B][H][S][HD]; one n-block == one head
        __half *Oh_, *Ol_; int Hh, hh;
        if (bx < 32)      { hh = bx;      Oh_ = Qh; Ol_ = Ql; Hh = NH_; }
        else if (bx < 40) { hh = bx - 32; Oh_ = Kh; Ol_ = Kl; Hh = NKV_; }
        else              { hh = bx - 40; Oh_ = Vh; Ol_ = Vl; Hh = NKV_; }
#pragma unroll
        for (int mt = 0; mt < 4; mt++) {
            int r = m0 + wm0 + mt * 16 + (lane >> 2);
            int b  = r >> 11;
            int s  = r & (S_ - 1);
            size_t base0 = (((size_t)(b * Hh + hh)) * S_ + s) * HD_;
            size_t base1 = (((size_t)(b * Hh + hh)) * S_ + s + 8) * HD_;
#pragma unroll
            for (int nt = 0; nt < 8; nt++) {
                int cl = wn0 + nt * 8 + (lane & 3) * 2;
                float a0 = acc[mt][nt][0], a1 = acc[mt][nt][1];
                float a2 = acc[mt][nt][2], a3 = acc[mt][nt][3];
                __half2 h01 = __floats2half2_rn(a0, a1);
                __half2 h23 = __floats2half2_rn(a2, a3);
                __half2 l01 = __floats2half2_rn(a0 - __low2float(h01),
                                                a1 - __high2float(h01));
                __half2 l23 = __floats2half2_rn(a2 - __low2float(h23),
                                                a3 - __high2float(h23));
                *(__half2*)&Oh_[base0 + cl] = h01;
                *(__half2*)&Ol_[base0 + cl] = l01;
                *(__half2*)&Oh_[base1 + cl] = h23;
                *(__half2*)&Ol_[base1 + cl] = l23;
            }
        }
    } else {
#pragma unroll
        for (int mt = 0; mt < 4; mt++) {
            int r = m0 + wm0 + mt * 16 + (lane >> 2);
#pragma unroll
            for (int nt = 0; nt < 8; nt++) {
                int cl = bx * 128 + wn0 + nt * 8 + (lane & 3) * 2;
                float* p0 = C + (size_t)r * Ntot + cl;
                *(float2*)p0 = make_float2(acc[mt][nt][0], acc[mt][nt][1]);
                float* p1 = C + (size_t)(r + 8) * Ntot + cl;
                *(float2*)p1 = make_float2(acc[mt][nt][2], acc[mt][nt][3]);
            }
        }
    }
}

// ======================= RoPE on hi/lo pairs =================================
__global__ void rope_pair(const __half* __restrict__ ih, const __half* __restrict__ il,
                          const float* __restrict__ cs, const float* __restrict__ sn,
                          __half* __restrict__ oh, __half* __restrict__ ol, int H)
{
    int s = blockIdx.x, h = blockIdx.y, b = blockIdx.z;
    int d = threadIdx.x;
    size_t base = ((size_t)(b * H + h) * S_ + s) * HD_;
    float x = __half2float(ih[base + d]) + __half2float(il[base + d]);
    int dp = (d < 64) ? d + 64 : d - 64;
    float o = __half2float(ih[base + dp]) + __half2float(il[base + dp]);
    if (d < 64) o = -o;
    size_t ci = ((size_t)b * S_ + s) * HD_ + d;
    float val = x * cs[ci] + o * sn[ci];
    __half hh = __float2half(val);
    oh[base + d] = hh;
    ol[base + d] = __float2half(val - __half2float(hh));
}

// ======================= HMMA flash attention ================================
// BQ=128 (8 warps x 16 rows), BK=64, fp16 x3 split, fp32 accum, causal.
// LPT scheduling: longest (largest-qt) CTAs launch first.
#define FROWB 272
#define FTILE (64 * FROWB)
#define QTILE (128 * FROWB)
#define FSMEM_BYTES (2 * QTILE + 8 * FTILE)

__global__ void __launch_bounds__(256)
flash16(const __half* __restrict__ Qh, const __half* __restrict__ Ql,
        const __half* __restrict__ Kh, const __half* __restrict__ Kl,
        const __half* __restrict__ Vh, const __half* __restrict__ Vl,
        __half* __restrict__ Oh, __half* __restrict__ Ol)
{
    extern __shared__ char smc[];
    const uint32_t sb = smem_u32(smc);
    const int qt = (int)gridDim.x - 1 - (int)blockIdx.x;   // LPT: heavy CTAs first
    const int h = blockIdx.y, b = blockIdx.z;
    const int kvh = h >> 2;
    const int tid = threadIdx.x, wid = tid >> 5, lane = tid & 31;
    const int q0 = qt * 128;
    const int tmax = 2 * qt + 1;
    const size_t qg  = ((size_t)(b * NH_ + h) * S_ + q0) * HD_;
    const size_t kvg = ((size_t)(b * NKV_ + kvh) * S_) * HD_;

#pragma unroll
    for (int u = 0; u < 16; u++) {
        int c = tid + u * 256;
        int comp = c >> 11, r = (c >> 4) & 127, ch = c & 15;
        const __half* src = (comp ? Ql : Qh) + qg + (size_t)r * HD_ + ch * 8;
        CP_ASYNC16(sb + comp * QTILE + r * FROWB + ch * 16, src);
    }
    auto load_kv = [&](int t, int st) {
        uint32_t base = sb + 2 * QTILE + st * 4 * FTILE;
        size_t g = kvg + (size_t)t * 64 * HD_;
#pragma unroll
        for (int u = 0; u < 16; u++) {
            int c = tid + u * 256;
            int comp = c >> 10, r = (c >> 4) & 63, ch = c & 15;
            const __half* src = (comp == 0 ? Kh : comp == 1 ? Kl
                               : comp == 2 ? Vh : Vl) + g + (size_t)r * HD_ + ch * 8;
            CP_ASYNC16(base + comp * FTILE + r * FROWB + ch * 16, src);
        }
        CP_COMMIT();
    };
    load_kv(0, 0);
    load_kv(1, 1);

    float oacc[16][4];
#pragma unroll
    for (int i = 0; i < 16; i++)
#pragma unroll
        for (int r = 0; r < 4; r++) oacc[i][r] = 0.0f;
    float mrun0 = -1e30f, mrun1 = -1e30f, lrun0 = 0.0f, lrun1 = 0.0f;

    const uint32_t qa_off = (uint32_t)(wid * 16 + (lane & 15)) * FROWB + (lane >> 4) * 16;
    const uint32_t ka_off = (uint32_t)(((lane >> 4) & 1) * 8 + (lane & 7)) * FROWB
                          + ((lane >> 3) & 1) * 16;
    const uint32_t va_off = (uint32_t)(lane & 15) * FROWB + ((lane >> 4) & 1) * 16;

    for (int t = 0; t <= tmax; t++) {
        if (t < tmax) { CP_WAIT(1); } else { CP_WAIT(0); }
        __syncthreads();
        uint32_t kb = sb + 2 * QTILE + (t & 1) * 4 * FTILE;
        uint32_t Khs = kb, Kls = kb + FTILE, Vhs = kb + 2 * FTILE, Vls = kb + 3 * FTILE;

        float sacc[8][4];
#pragma unroll
        for (int i = 0; i < 8; i++)
#pragma unroll
            for (int r = 0; r < 4; r++) sacc[i][r] = 0.0f;

#pragma unroll
        for (int j = 0; j < 8; j++) {
            uint32_t qo = qa_off + j * 32;
            uint32_t qhf[4], qlf[4];
            LDSM4(qhf[0], qhf[1], qhf[2], qhf[3], sb + qo);
            LDSM4(qlf[0], qlf[1], qlf[2], qlf[3], sb + QTILE + qo);
#pragma unroll
            for (int p = 0; p < 4; p++) {
                uint32_t ko = ka_off + p * 16 * FROWB + j * 32;
                uint32_t khf[4], klf[4];
                LDSM4(khf[0], khf[1], khf[2], khf[3], Khs + ko);
                LDSM4(klf[0], klf[1], klf[2], klf[3], Kls + ko);
                MMA16816(sacc[2*p],   qhf, khf);
                MMA16816(sacc[2*p],   qhf, klf);
                MMA16816(sacc[2*p],   qlf, khf);
                MMA16816(sacc[2*p+1], qhf, khf + 2);
                MMA16816(sacc[2*p+1], qhf, klf + 2);
                MMA16816(sacc[2*p+1], qlf, khf + 2);
            }
        }

#pragma unroll
        for (int j = 0; j < 8; j++)
#pragma unroll
            for (int r = 0; r < 4; r++) sacc[j][r] *= SCALE_;

        if (t >= 2 * qt) {
            int rg = q0 + wid * 16 + (lane >> 2);
#pragma unroll
            for (int j = 0; j < 8; j++) {
                int cg = 64 * t + 8 * j + (lane & 3) * 2;
                if (cg     > rg)     sacc[j][0] = -1e30f;
                if (cg + 1 > rg)     sacc[j][1] = -1e30f;
                if (cg     > rg + 8) sacc[j][2] = -1e30f;
                if (cg + 1 > rg + 8) sacc[j][3] = -1e30f;
            }
        }
        float mx0 = -1e30f, mx1 = -1e30f;
#pragma unroll
        for (int j = 0; j < 8; j++) {
            mx0 = fmaxf(mx0, fmaxf(sacc[j][0], sacc[j][1]));
            mx1 = fmaxf(mx1, fmaxf(sacc[j][2], sacc[j][3]));
        }
        mx0 = fmaxf(mx0, __shfl_xor_sync(0xffffffffu, mx0, 1));
        mx0 = fmaxf(mx0, __shfl_xor_sync(0xffffffffu, mx0, 2));
        mx1 = fmaxf(mx1, __shfl_xor_sync(0xffffffffu, mx1, 1));
        mx1 = fmaxf(mx1, __shfl_xor_sync(0xffffffffu, mx1, 2));
        float mn0 = fmaxf(mrun0, mx0), mn1 = fmaxf(mrun1, mx1);
        float al0 = __expf(mrun0 - mn0), al1 = __expf(mrun1 - mn1);

        uint32_t ph[8][2], pl[8][2];
        float l0 = 0.0f, l1 = 0.0f;
#pragma unroll
        for (int j = 0; j < 8; j++) {
            float p0 = __expf(sacc[j][0] - mn0), p1 = __expf(sacc[j][1] - mn0);
            float p2 = __expf(sacc[j][2] - mn1), p3 = __expf(sacc[j][3] - mn1);
            l0 += p0 + p1; l1 += p2 + p3;
            __half2 h01 = __floats2half2_rn(p0, p1);
            __half2 h23 = __floats2half2_rn(p2, p3);
            ph[j][0] = *(uint32_t*)&h01;
            ph[j][1] = *(uint32_t*)&h23;
            __half2 r01 = __floats2half2_rn(p0 - __low2float(h01), p1 - __high2float(h01));
            __half2 r23 = __floats2half2_rn(p2 - __low2float(h23), p3 - __high2float(h23));
            pl[j][0] = *(uint32_t*)&r01;
            pl[j][1] = *(uint32_t*)&r23;
        }
        l0 += __shfl_xor_sync(0xffffffffu, l0, 1);
        l0 += __shfl_xor_sync(0xffffffffu, l0, 2);
        l1 += __shfl_xor_sync(0xffffffffu, l1, 1);
        l1 += __shfl_xor_sync(0xffffffffu, l1, 2);
        lrun0 = lrun0 * al0 + l0; lrun1 = lrun1 * al1 + l1;
        mrun0 = mn0; mrun1 = mn1;
#pragma unroll
        for (int nt = 0; nt < 16; nt++) {
            oacc[nt][0] *= al0; oacc[nt][1] *= al0;
            oacc[nt][2] *= al1; oacc[nt][3] *= al1;
        }

#pragma unroll
        for (int jc = 0; jc < 4; jc++) {
            uint32_t pfh[4] = {ph[2*jc][0], ph[2*jc][1], ph[2*jc+1][0], ph[2*jc+1][1]};
            uint32_t pfl[4] = {pl[2*jc][0], pl[2*jc][1], pl[2*jc+1][0], pl[2*jc+1][1]};
#pragma unroll
            for (int dp = 0; dp < 8; dp++) {
                uint32_t vo = va_off + jc * 16 * FROWB + dp * 32;
                uint32_t vhf[4], vlf[4];
                LDSM4T(vhf[0], vhf[1], vhf[2], vhf[3], Vhs + vo);
                LDSM4T(vlf[0], vlf[1], vlf[2], vlf[3], Vls + vo);
                MMA16816(oacc[2*dp],   pfh, vhf);
                MMA16816(oacc[2*dp],   pfh, vlf);
                MMA16816(oacc[2*dp],   pfl, vhf);
                MMA16816(oacc[2*dp+1], pfh, vhf + 2);
                MMA16816(oacc[2*dp+1], pfh, vlf + 2);
                MMA16816(oacc[2*dp+1], pfl, vhf + 2);
            }
        }
        __syncthreads();
        if (t + 2 <= tmax) load_kv(t + 2, t & 1);
    }

    float inv0 = 1.0f / lrun0, inv1 = 1.0f / lrun1;
    int r0 = q0 + wid * 16 + (lane >> 2);
    size_t ob0 = ((size_t)(b * S_ + r0)) * (NH_ * HD_) + h * HD_;
    size_t ob1 = ((size_t)(b * S_ + r0 + 8)) * (NH_ * HD_) + h * HD_;
#pragma unroll
    for (int nt = 0; nt < 16; nt++) {
        int col = nt * 8 + (lane & 3) * 2;
        float f0 = oacc[nt][0] * inv0, f1 = oacc[nt][1] * inv0;
        float f2 = oacc[nt][2] * inv1, f3 = oacc[nt][3] * inv1;
        __half2 h01 = __floats2half2_rn(f0, f1);
        __half2 h23 = __floats2half2_rn(f2, f3);
        __half2 l01 = __floats2half2_rn(f0 - __low2float(h01), f1 - __high2float(h01));
        __half2 l23 = __floats2half2_rn(f2 - __low2float(h23), f3 - __high2float(h23));
        *(__half2*)&Oh[ob0 + col] = h01;
        *(__half2*)&Ol[ob0 + col] = l01;
        *(__half2*)&Oh[ob1 + col] = h23;
        *(__half2*)&Ol[ob1 + col] = l23;
    }
}

// ======================= launch ==============================================
extern "C" void kernel_launch(void* const* d_in, const int* in_sizes, int n_in,
                              void* d_out, int out_size)
{
    (void)in_sizes; (void)n_in; (void)out_size;
    const float* hs = (const float*)d_in[0];
    const float* cs = (const float*)d_in[1];
    const float* sn = (const float*)d_in[2];
    const float* Wq = (const float*)d_in[4];
    const float* Wk = (const float*)d_in[5];
    const float* Wv = (const float*)d_in[6];
    const float* Wo = (const float*)d_in[7];
    float* out = (float*)d_out;

    __half *hsh, *hsl, *wqh, *wql, *wkh, *wkl, *wvh, *wvl, *woh, *wol, *oh, *ol;
    __half *qh, *ql, *kh, *kl, *vh, *vl, *qrh, *qrl, *krh, *krl;
    cudaGetSymbolAddress((void**)&hsh, g_hs_h); cudaGetSymbolAddress((void**)&hsl, g_hs_l);
    cudaGetSymbolAddress((void**)&wqh, g_wq_h); cudaGetSymbolAddress((void**)&wql, g_wq_l);
    cudaGetSymbolAddress((void**)&wkh, g_wk_h); cudaGetSymbolAddress((void**)&wkl, g_wk_l);
    cudaGetSymbolAddress((void**)&wvh, g_wv_h); cudaGetSymbolAddress((void**)&wvl, g_wv_l);
    cudaGetSymbolAddress((void**)&woh, g_wo_h); cudaGetSymbolAddress((void**)&wol, g_wo_l);
    cudaGetSymbolAddress((void**)&oh,  g_o_h);  cudaGetSymbolAddress((void**)&ol,  g_o_l);
    cudaGetSymbolAddress((void**)&qh,  g_qh);   cudaGetSymbolAddress((void**)&ql,  g_ql);
    cudaGetSymbolAddress((void**)&kh,  g_kh);   cudaGetSymbolAddress((void**)&kl,  g_kl);
    cudaGetSymbolAddress((void**)&vh,  g_vh);   cudaGetSymbolAddress((void**)&vl,  g_vl);
    cudaGetSymbolAddress((void**)&qrh, g_qrh);  cudaGetSymbolAddress((void**)&qrl, g_qrl);
    cudaGetSymbolAddress((void**)&krh, g_krh);  cudaGetSymbolAddress((void**)&krl, g_krl);

    const int n_big = 4096 * 4096 / 4, n_sm = 1024 * 4096 / 4;
    split_hilo<<<(n_big + 255) / 256, 256>>>(hs, hsh, hsl, n_big);
    split_hilo<<<(n_big + 255) / 256, 256>>>(Wq, wqh, wql, n_big);
    split_hilo<<<(n_sm + 255) / 256, 256>>>(Wk, wkh, wkl, n_sm);
    split_hilo<<<(n_sm + 255) / 256, 256>>>(Wv, wvh, wvl, n_sm);
    split_hilo<<<(n_big + 255) / 256, 256>>>(Wo, woh, wol, n_big);

    cudaFuncSetAttribute(gemm3_h16<0>,
                         cudaFuncAttributeMaxDynamicSharedMemorySize, GSMEM_BYTES);
    cudaFuncSetAttribute(gemm3_h16<2>,
                         cudaFuncAttributeMaxDynamicSharedMemorySize, GSMEM_BYTES);

    // fused QKV projection: 32 Q blocks + 8 K + 8 V, hi/lo head-layout out
    gemm3_h16<2><<<dim3(48, 16), 256, GSMEM_BYTES>>>(
        hsh, hsl, wqh, wql, wkh, wkl, wvh, wvl,
        nullptr, 4096, 0, qh, ql, kh, kl, vh, vl);

    rope_pair<<<dim3(S_, NH_, B_),  128>>>(qh, ql, cs, sn, qrh, qrl, NH_);
    rope_pair<<<dim3(S_, NKV_, B_), 128>>>(kh, kl, cs, sn, krh, krl, NKV_);

    cudaFuncSetAttribute(flash16,
                         cudaFuncAttributeMaxDynamicSharedMemorySize, FSMEM_BYTES);
    flash16<<<dim3(S_ / 128, NH_, B_), 256, FSMEM_BYTES>>>(
        qrh, qrl, krh, krl, vh, vl, oh, ol);

    // output projection: fp32 flat out
    gemm3_h16<0><<<dim3(32, 16), 256, GSMEM_BYTES>>>(
        oh, ol, woh, wol, nullptr, nullptr, nullptr, nullptr,
        out, 4096, 4096, nullptr, nullptr, nullptr, nullptr, nullptr, nullptr);
}

// round 16
// speedup vs baseline: 1.0487x; 1.0242x over previous
#include <cuda_runtime.h>
#include <cuda_fp16.h>
#include <math.h>
#include <stdint.h>

#define B_    2
#define S_    2048
#define HID_  4096
#define NH_   32
#define NKV_  8
#define HD_   128
#define SCALE_ 0.08838834764831845f   // 128^-0.5

// ======================= PTX helpers ========================================
__device__ __forceinline__ uint32_t smem_u32(const void* p) {
    uint32_t a;
    asm("{ .reg .u64 t; cvta.to.shared.u64 t, %1; cvt.u32.u64 %0, t; }"
        : "=r"(a) : "l"(p));
    return a;
}
#define CP_ASYNC16(dst, src) \
    asm volatile("cp.async.cg.shared.global [%0], [%1], 16;" :: "r"(dst), "l"(src))
#define CP_COMMIT() asm volatile("cp.async.commit_group;" ::: "memory")
#define CP_WAIT(n)  asm volatile("cp.async.wait_group %0;" :: "n"(n) : "memory")

#define LDSM4(r0, r1, r2, r3, a)                                              \
    asm volatile("ldmatrix.sync.aligned.m8n8.x4.shared.b16 {%0,%1,%2,%3}, [%4];" \
        : "=r"(r0), "=r"(r1), "=r"(r2), "=r"(r3) : "r"(a))
#define LDSM4T(r0, r1, r2, r3, a)                                             \
    asm volatile("ldmatrix.sync.aligned.m8n8.x4.trans.shared.b16 {%0,%1,%2,%3}, [%4];" \
        : "=r"(r0), "=r"(r1), "=r"(r2), "=r"(r3) : "r"(a))

#define MMA16816(c, av, bv)                                                   \
    asm volatile("mma.sync.aligned.m16n8k16.row.col.f32.f16.f16.f32 "         \
        "{%0,%1,%2,%3}, {%4,%5,%6,%7}, {%8,%9}, {%0,%1,%2,%3};"               \
        : "+f"((c)[0]), "+f"((c)[1]), "+f"((c)[2]), "+f"((c)[3])              \
        : "r"((av)[0]), "r"((av)[1]), "r"((av)[2]), "r"((av)[3]),             \
          "r"((bv)[0]), "r"((bv)[1]))

// ======================= scratch ============================================
__device__ __half g_hs_h[4096 * 4096], g_hs_l[4096 * 4096];
__device__ __half g_wq_h[4096 * 4096], g_wq_l[4096 * 4096];
__device__ __half g_wk_h[1024 * 4096], g_wk_l[1024 * 4096];
__device__ __half g_wv_h[1024 * 4096], g_wv_l[1024 * 4096];
__device__ __half g_wo_h[4096 * 4096], g_wo_l[4096 * 4096];
__device__ __half g_o_h [4096 * 4096], g_o_l [4096 * 4096];
// projection outputs (Q/K rope'd in GEMM epilogue), head layout [B,H,S,HD]
__device__ __half g_qh [B_ * NH_  * S_ * HD_], g_ql [B_ * NH_  * S_ * HD_];
__device__ __half g_kh [B_ * NKV_ * S_ * HD_], g_kl [B_ * NKV_ * S_ * HD_];
__device__ __half g_vh [B_ * NKV_ * S_ * HD_], g_vl [B_ * NKV_ * S_ * HD_];

// ======================= split fp32 -> fp16 hi/lo ============================
__global__ void __launch_bounds__(256)
split_hilo(const float* __restrict__ x, __half* __restrict__ hi,
           __half* __restrict__ lo, int n4)
{
    int i = blockIdx.x * blockDim.x + threadIdx.x;
    if (i >= n4) return;
    float4 v = ((const float4*)x)[i];
    __half h0 = __float2half(v.x), h1 = __float2half(v.y);
    __half h2 = __float2half(v.z), h3 = __float2half(v.w);
    __half l0 = __float2half(v.x - __half2float(h0));
    __half l1 = __float2half(v.y - __half2float(h1));
    __half l2 = __float2half(v.z - __half2float(h2));
    __half l3 = __float2half(v.w - __half2float(h3));
    ((__half2*)hi)[2 * i + 0] = __halves2half2(h0, h1);
    ((__half2*)hi)[2 * i + 1] = __halves2half2(h2, h3);
    ((__half2*)lo)[2 * i + 0] = __halves2half2(l0, l1);
    ((__half2*)lo)[2 * i + 1] = __halves2half2(l2, l3);
}

// ======================= HMMA fp16x3 GEMM ====================================
// CTA 256x128, 8 warps (4m x 2n), warp tile 64x64, K-tile 64, double buffer.
// MODE 0: C fp32 flat [M, Ntot]
// MODE 2: fused QKV — B select by blockIdx.x; epilogue applies RoPE to Q/K
//         via smem-staged tile with COALESCED cos/sin access, writes hi/lo
//         fp16 in head layout. V blocks write direct from registers.
#define ROWB  144                     // 72 halfs row stride (64 data + 8 pad)
#define ATILEB (256 * ROWB)           // 36864 B
#define BTILEB (128 * ROWB)           // 18432 B
#define STAGEB (2 * ATILEB + 2 * BTILEB) // 110592 B
#define GSMEM_BYTES (2 * STAGEB)      // 221184 B
#define EPI_STRIDE 132                // fp32 epilogue tile stride (floats)

template <int MODE>
__global__ void __launch_bounds__(256)
gemm3_h16(const __half* __restrict__ Ah, const __half* __restrict__ Al,
          const __half* __restrict__ Bqh, const __half* __restrict__ Bql,
          const __half* __restrict__ Bkh, const __half* __restrict__ Bkl,
          const __half* __restrict__ Bvh, const __half* __restrict__ Bvl,
          const float* __restrict__ Cs, const float* __restrict__ Sn,
          float* __restrict__ C, int K, int Ntot,
          __half* __restrict__ Qh, __half* __restrict__ Ql,
          __half* __restrict__ Kh, __half* __restrict__ Kl,
          __half* __restrict__ Vh, __half* __restrict__ Vl)
{
    extern __shared__ char smem[];
    const uint32_t sbase = smem_u32(smem);
    const int tid  = threadIdx.x;
    const int wid  = tid >> 5;
    const int lane = tid & 31;
    const int bx = blockIdx.x;
    const int m0 = blockIdx.y * 256;
    const int wm0 = (wid & 3) * 64;
    const int wn0 = (wid >> 2) * 64;
    const int niter = K >> 6;

    const __half *Bh_, *Bl_;
    int n0;
    if (MODE == 2) {
        if (bx < 32)      { Bh_ = Bqh; Bl_ = Bql; n0 = bx * 128; }
        else if (bx < 40) { Bh_ = Bkh; Bl_ = Bkl; n0 = (bx - 32) * 128; }
        else              { Bh_ = Bvh; Bl_ = Bvl; n0 = (bx - 40) * 128; }
    } else {
        Bh_ = Bqh; Bl_ = Bql; n0 = bx * 128;
    }

    float acc[4][8][4];
#pragma unroll
    for (int i = 0; i < 4; i++)
#pragma unroll
        for (int j = 0; j < 8; j++)
#pragma unroll
            for (int r = 0; r < 4; r++) acc[i][j][r] = 0.0f;

    auto load_stage = [&](int it, int st) {
        uint32_t base = sbase + st * STAGEB;
        int kt = it << 6;
#pragma unroll
        for (int u = 0; u < 8; u++) {
            int c = tid + u * 256;
            int row = c >> 3, seg = c & 7;
            uint32_t o = (uint32_t)row * ROWB + seg * 16;
            size_t go = (size_t)(m0 + row) * K + kt + seg * 8;
            CP_ASYNC16(base + o,          Ah + go);
            CP_ASYNC16(base + ATILEB + o, Al + go);
        }
#pragma unroll
        for (int u = 0; u < 4; u++) {
            int c = tid + u * 256;
            int row = c >> 3, seg = c & 7;
            uint32_t o = (uint32_t)row * ROWB + seg * 16;
            size_t go = (size_t)(n0 + row) * K + kt + seg * 8;
            CP_ASYNC16(base + 2 * ATILEB + o,          Bh_ + go);
            CP_ASYNC16(base + 2 * ATILEB + BTILEB + o, Bl_ + go);
        }
        CP_COMMIT();
    };

    const uint32_t a_off = (uint32_t)(wm0 + (lane & 15)) * ROWB + (lane >> 4) * 16;
    const uint32_t b_off = (uint32_t)(wn0 + ((lane >> 4) & 1) * 8 + (lane & 7)) * ROWB
                         + ((lane >> 3) & 1) * 16;

    load_stage(0, 0);
    for (int it = 0; it < niter; it++) {
        if (it + 1 < niter) { load_stage(it + 1, (it + 1) & 1); CP_WAIT(1); }
        else                { CP_WAIT(0); }
        __syncthreads();

        uint32_t tb = sbase + (it & 1) * STAGEB;
        uint32_t As_h = tb, As_l = tb + ATILEB;
        uint32_t Bs_h = tb + 2 * ATILEB, Bs_l = tb + 2 * ATILEB + BTILEB;

#pragma unroll
        for (int k16 = 0; k16 < 4; k16++) {
            uint32_t kb = k16 * 32;
            uint32_t ah[4][4], al[4][4];
#pragma unroll
            for (int mt = 0; mt < 4; mt++) {
                uint32_t o = a_off + mt * 16 * ROWB + kb;
                LDSM4(ah[mt][0], ah[mt][1], ah[mt][2], ah[mt][3], As_h + o);
                LDSM4(al[mt][0], al[mt][1], al[mt][2], al[mt][3], As_l + o);
            }
#pragma unroll
            for (int np = 0; np < 4; np++) {
                uint32_t o = b_off + np * 16 * ROWB + kb;
                uint32_t bh[4], bl[4];
                LDSM4(bh[0], bh[1], bh[2], bh[3], Bs_h + o);
                LDSM4(bl[0], bl[1], bl[2], bl[3], Bs_l + o);
#pragma unroll
                for (int mt = 0; mt < 4; mt++) {
                    MMA16816(acc[mt][2*np],   ah[mt], bh);
                    MMA16816(acc[mt][2*np],   ah[mt], bl);
                    MMA16816(acc[mt][2*np],   al[mt], bh);
                    MMA16816(acc[mt][2*np+1], ah[mt], bh + 2);
                    MMA16816(acc[mt][2*np+1], ah[mt], bl + 2);
                    MMA16816(acc[mt][2*np+1], al[mt], bh + 2);
                }
            }
        }
        __syncthreads();
    }

    if (MODE == 2) {
        __half *Oh_, *Ol_; int Hh, hh; bool rope;
        if (bx < 32)      { hh = bx;      Oh_ = Qh; Ol_ = Ql; Hh = NH_;  rope = true; }
        else if (bx < 40) { hh = bx - 32; Oh_ = Kh; Ol_ = Kl; Hh = NKV_; rope = true; }
        else              { hh = bx - 40; Oh_ = Vh; Ol_ = Vl; Hh = NKV_; rope = false; }

        if (!rope) {
            // V: direct from registers (already coalesced) — R8 path
#pragma unroll
            for (int mt = 0; mt < 4; mt++) {
                int r = m0 + wm0 + mt * 16 + (lane >> 2);
                int b  = r >> 11;
                int s  = r & (S_ - 1);
                size_t base0 = (((size_t)(b * Hh + hh)) * S_ + s) * HD_;
                size_t base1 = (((size_t)(b * Hh + hh)) * S_ + s + 8) * HD_;
#pragma unroll
                for (int nt = 0; nt < 8; nt++) {
                    int cl = wn0 + nt * 8 + (lane & 3) * 2;
                    float a0 = acc[mt][nt][0], a1 = acc[mt][nt][1];
                    float a2 = acc[mt][nt][2], a3 = acc[mt][nt][3];
                    __half2 h01 = __floats2half2_rn(a0, a1);
                    __half2 h23 = __floats2half2_rn(a2, a3);
                    __half2 l01 = __floats2half2_rn(a0 - __low2float(h01),
                                                    a1 - __high2float(h01));
                    __half2 l23 = __floats2half2_rn(a2 - __low2float(h23),
                                                    a3 - __high2float(h23));
                    *(__half2*)&Oh_[base0 + cl] = h01;
                    *(__half2*)&Ol_[base0 + cl] = l01;
                    *(__half2*)&Oh_[base1 + cl] = h23;
                    *(__half2*)&Ol_[base1 + cl] = l23;
                }
            }
        } else {
            // Q/K: stage fp32 tile in smem, then coalesced rope pass
            float* ft = (float*)smem;
#pragma unroll
            for (int mt = 0; mt < 4; mt++) {
                int r = wm0 + mt * 16 + (lane >> 2);
#pragma unroll
                for (int nt = 0; nt < 8; nt++) {
                    int cl = wn0 + nt * 8 + (lane & 3) * 2;
                    *(float2*)&ft[(size_t)r * EPI_STRIDE + cl] =
                        make_float2(acc[mt][nt][0], acc[mt][nt][1]);
                    *(float2*)&ft[(size_t)(r + 8) * EPI_STRIDE + cl] =
                        make_float2(acc[mt][nt][2], acc[mt][nt][3]);
                }
            }
            __syncthreads();

            // coalesced pass: warp w handles rows p*8+w; lane handles the
            // rope pair (da = lane*2, db = da+64) as float2.
            const int da = lane * 2;       // 0..62
            const int db = da + 64;        // 64..126
#pragma unroll
            for (int p = 0; p < 32; p++) {
                int r = p * 8 + wid;       // 0..255
                int m = m0 + r;
                int b = m >> 11;
                int s = m & (S_ - 1);
                const float* fr = ft + (size_t)r * EPI_STRIDE;
                size_t ob = (((size_t)(b * Hh + hh)) * S_ + s) * HD_;
                size_t ci = ((size_t)(b * S_ + s)) * HD_;

                float2 xa = *(const float2*)&fr[da];
                float2 xb = *(const float2*)&fr[db];
                float2 ca = *(const float2*)&Cs[ci + da];
                float2 cb = *(const float2*)&Cs[ci + db];
                float2 sa = *(const float2*)&Sn[ci + da];
                float2 sb = *(const float2*)&Sn[ci + db];

                float oa0 = xa.x * ca.x - xb.x * sa.x;
                float oa1 = xa.y * ca.y - xb.y * sa.y;
                float ob0 = xb.x * cb.x + xa.x * sb.x;
                float ob1 = xb.y * cb.y + xa.y * sb.y;

                __half2 ha = __floats2half2_rn(oa0, oa1);
                __half2 la = __floats2half2_rn(oa0 - __low2float(ha),
                                               oa1 - __high2float(ha));
                __half2 hb = __floats2half2_rn(ob0, ob1);
                __half2 lb = __floats2half2_rn(ob0 - __low2float(hb),
                                               ob1 - __high2float(hb));
                *(__half2*)&Oh_[ob + da] = ha;
                *(__half2*)&Ol_[ob + da] = la;
                *(__half2*)&Oh_[ob + db] = hb;
                *(__half2*)&Ol_[ob + db] = lb;
            }
        }
    } else {
#pragma unroll
        for (int mt = 0; mt < 4; mt++) {
            int r = m0 + wm0 + mt * 16 + (lane >> 2);
#pragma unroll
            for (int nt = 0; nt < 8; nt++) {
                int cl = bx * 128 + wn0 + nt * 8 + (lane & 3) * 2;
                float* p0 = C + (size_t)r * Ntot + cl;
                *(float2*)p0 = make_float2(acc[mt][nt][0], acc[mt][nt][1]);
                float* p1 = C + (size_t)(r + 8) * Ntot + cl;
                *(float2*)p1 = make_float2(acc[mt][nt][2], acc[mt][nt][3]);
            }
        }
    }
}

// ======================= HMMA flash attention ================================
// BQ=128 (8 warps x 16 rows), BK=64, fp16 x3 split, fp32 accum, causal.
// LPT scheduling: longest (largest-qt) CTAs launch first.
#define FROWB 272
#define FTILE (64 * FROWB)
#define QTILE (128 * FROWB)
#define FSMEM_BYTES (2 * QTILE + 8 * FTILE)

__global__ void __launch_bounds__(256)
flash16(const __half* __restrict__ Qh, const __half* __restrict__ Ql,
        const __half* __restrict__ Kh, const __half* __restrict__ Kl,
        const __half* __restrict__ Vh, const __half* __restrict__ Vl,
        __half* __restrict__ Oh, __half* __restrict__ Ol)
{
    extern __shared__ char smc[];
    const uint32_t sb = smem_u32(smc);
    const int qt = (int)gridDim.x - 1 - (int)blockIdx.x;   // LPT: heavy CTAs first
    const int h = blockIdx.y, b = blockIdx.z;
    const int kvh = h >> 2;
    const int tid = threadIdx.x, wid = tid >> 5, lane = tid & 31;
    const int q0 = qt * 128;
    const int tmax = 2 * qt + 1;
    const size_t qg  = ((size_t)(b * NH_ + h) * S_ + q0) * HD_;
    const size_t kvg = ((size_t)(b * NKV_ + kvh) * S_) * HD_;

#pragma unroll
    for (int u = 0; u < 16; u++) {
        int c = tid + u * 256;
        int comp = c >> 11, r = (c >> 4) & 127, ch = c & 15;
        const __half* src = (comp ? Ql : Qh) + qg + (size_t)r * HD_ + ch * 8;
        CP_ASYNC16(sb + comp * QTILE + r * FROWB + ch * 16, src);
    }
    auto load_kv = [&](int t, int st) {
        uint32_t base = sb + 2 * QTILE + st * 4 * FTILE;
        size_t g = kvg + (size_t)t * 64 * HD_;
#pragma unroll
        for (int u = 0; u < 16; u++) {
            int c = tid + u * 256;
            int comp = c >> 10, r = (c >> 4) & 63, ch = c & 15;
            const __half* src = (comp == 0 ? Kh : comp == 1 ? Kl
                               : comp == 2 ? Vh : Vl) + g + (size_t)r * HD_ + ch * 8;
            CP_ASYNC16(base + comp * FTILE + r * FROWB + ch * 16, src);
        }
        CP_COMMIT();
    };
    load_kv(0, 0);
    load_kv(1, 1);

    float oacc[16][4];
#pragma unroll
    for (int i = 0; i < 16; i++)
#pragma unroll
        for (int r = 0; r < 4; r++) oacc[i][r] = 0.0f;
    float mrun0 = -1e30f, mrun1 = -1e30f, lrun0 = 0.0f, lrun1 = 0.0f;

    const uint32_t qa_off = (uint32_t)(wid * 16 + (lane & 15)) * FROWB + (lane >> 4) * 16;
    const uint32_t ka_off = (uint32_t)(((lane >> 4) & 1) * 8 + (lane & 7)) * FROWB
                          + ((lane >> 3) & 1) * 16;
    const uint32_t va_off = (uint32_t)(lane & 15) * FROWB + ((lane >> 4) & 1) * 16;

    for (int t = 0; t <= tmax; t++) {
        if (t < tmax) { CP_WAIT(1); } else { CP_WAIT(0); }
        __syncthreads();
        uint32_t kb = sb + 2 * QTILE + (t & 1) * 4 * FTILE;
        uint32_t Khs = kb, Kls = kb + FTILE, Vhs = kb + 2 * FTILE, Vls = kb + 3 * FTILE;

        float sacc[8][4];
#pragma unroll
        for (int i = 0; i < 8; i++)
#pragma unroll
            for (int r = 0; r < 4; r++) sacc[i][r] = 0.0f;

#pragma unroll
        for (int j = 0; j < 8; j++) {
            uint32_t qo = qa_off + j * 32;
            uint32_t qhf[4], qlf[4];
            LDSM4(qhf[0], qhf[1], qhf[2], qhf[3], sb + qo);
            LDSM4(qlf[0], qlf[1], qlf[2], qlf[3], sb + QTILE + qo);
#pragma unroll
            for (int p = 0; p < 4; p++) {
                uint32_t ko = ka_off + p * 16 * FROWB + j * 32;
                uint32_t khf[4], klf[4];
                LDSM4(khf[0], khf[1], khf[2], khf[3], Khs + ko);
                LDSM4(klf[0], klf[1], klf[2], klf[3], Kls + ko);
                MMA16816(sacc[2*p],   qhf, khf);
                MMA16816(sacc[2*p],   qhf, klf);
                MMA16816(sacc[2*p],   qlf, khf);
                MMA16816(sacc[2*p+1], qhf, khf + 2);
                MMA16816(sacc[2*p+1], qhf, klf + 2);
                MMA16816(sacc[2*p+1], qlf, khf + 2);
            }
        }

#pragma unroll
        for (int j = 0; j < 8; j++)
#pragma unroll
            for (int r = 0; r < 4; r++) sacc[j][r] *= SCALE_;

        if (t >= 2 * qt) {
            int rg = q0 + wid * 16 + (lane >> 2);
#pragma unroll
            for (int j = 0; j < 8; j++) {
                int cg = 64 * t + 8 * j + (lane & 3) * 2;
                if (cg     > rg)     sacc[j][0] = -1e30f;
                if (cg + 1 > rg)     sacc[j][1] = -1e30f;
                if (cg     > rg + 8) sacc[j][2] = -1e30f;
                if (cg + 1 > rg + 8) sacc[j][3] = -1e30f;
            }
        }
        float mx0 = -1e30f, mx1 = -1e30f;
#pragma unroll
        for (int j = 0; j < 8; j++) {
            mx0 = fmaxf(mx0, fmaxf(sacc[j][0], sacc[j][1]));
            mx1 = fmaxf(mx1, fmaxf(sacc[j][2], sacc[j][3]));
        }
        mx0 = fmaxf(mx0, __shfl_xor_sync(0xffffffffu, mx0, 1));
        mx0 = fmaxf(mx0, __shfl_xor_sync(0xffffffffu, mx0, 2));
        mx1 = fmaxf(mx1, __shfl_xor_sync(0xffffffffu, mx1, 1));
        mx1 = fmaxf(mx1, __shfl_xor_sync(0xffffffffu, mx1, 2));
        float mn0 = fmaxf(mrun0, mx0), mn1 = fmaxf(mrun1, mx1);
        float al0 = __expf(mrun0 - mn0), al1 = __expf(mrun1 - mn1);

        uint32_t ph[8][2], pl[8][2];
        float l0 = 0.0f, l1 = 0.0f;
#pragma unroll
        for (int j = 0; j < 8; j++) {
            float p0 = __expf(sacc[j][0] - mn0), p1 = __expf(sacc[j][1] - mn0);
            float p2 = __expf(sacc[j][2] - mn1), p3 = __expf(sacc[j][3] - mn1);
            l0 += p0 + p1; l1 += p2 + p3;
            __half2 h01 = __floats2half2_rn(p0, p1);
            __half2 h23 = __floats2half2_rn(p2, p3);
            ph[j][0] = *(uint32_t*)&h01;
            ph[j][1] = *(uint32_t*)&h23;
            __half2 r01 = __floats2half2_rn(p0 - __low2float(h01), p1 - __high2float(h01));
            __half2 r23 = __floats2half2_rn(p2 - __low2float(h23), p3 - __high2float(h23));
            pl[j][0] = *(uint32_t*)&r01;
            pl[j][1] = *(uint32_t*)&r23;
        }
        l0 += __shfl_xor_sync(0xffffffffu, l0, 1);
        l0 += __shfl_xor_sync(0xffffffffu, l0, 2);
        l1 += __shfl_xor_sync(0xffffffffu, l1, 1);
        l1 += __shfl_xor_sync(0xffffffffu, l1, 2);
        lrun0 = lrun0 * al0 + l0; lrun1 = lrun1 * al1 + l1;
        mrun0 = mn0; mrun1 = mn1;
#pragma unroll
        for (int nt = 0; nt < 16; nt++) {
            oacc[nt][0] *= al0; oacc[nt][1] *= al0;
            oacc[nt][2] *= al1; oacc[nt][3] *= al1;
        }

#pragma unroll
        for (int jc = 0; jc < 4; jc++) {
            uint32_t pfh[4] = {ph[2*jc][0], ph[2*jc][1], ph[2*jc+1][0], ph[2*jc+1][1]};
            uint32_t pfl[4] = {pl[2*jc][0], pl[2*jc][1], pl[2*jc+1][0], pl[2*jc+1][1]};
#pragma unroll
            for (int dp = 0; dp < 8; dp++) {
                uint32_t vo = va_off + jc * 16 * FROWB + dp * 32;
                uint32_t vhf[4], vlf[4];
                LDSM4T(vhf[0], vhf[1], vhf[2], vhf[3], Vhs + vo);
                LDSM4T(vlf[0], vlf[1], vlf[2], vlf[3], Vls + vo);
                MMA16816(oacc[2*dp],   pfh, vhf);
                MMA16816(oacc[2*dp],   pfh, vlf);
                MMA16816(oacc[2*dp],   pfl, vhf);
                MMA16816(oacc[2*dp+1], pfh, vhf + 2);
                MMA16816(oacc[2*dp+1], pfh, vlf + 2);
                MMA16816(oacc[2*dp+1], pfl, vhf + 2);
            }
        }
        __syncthreads();
        if (t + 2 <= tmax) load_kv(t + 2, t & 1);
    }

    float inv0 = 1.0f / lrun0, inv1 = 1.0f / lrun1;
    int r0 = q0 + wid * 16 + (lane >> 2);
    size_t ob0 = ((size_t)(b * S_ + r0)) * (NH_ * HD_) + h * HD_;
    size_t ob1 = ((size_t)(b * S_ + r0 + 8)) * (NH_ * HD_) + h * HD_;
#pragma unroll
    for (int nt = 0; nt < 16; nt++) {
        int col = nt * 8 + (lane & 3) * 2;
        float f0 = oacc[nt][0] * inv0, f1 = oacc[nt][1] * inv0;
        float f2 = oacc[nt][2] * inv1, f3 = oacc[nt][3] * inv1;
        __half2 h01 = __floats2half2_rn(f0, f1);
        __half2 h23 = __floats2half2_rn(f2, f3);
        __half2 l01 = __floats2half2_rn(f0 - __low2float(h01), f1 - __high2float(h01));
        __half2 l23 = __floats2half2_rn(f2 - __low2float(h23), f3 - __high2float(h23));
        *(__half2*)&Oh[ob0 + col] = h01;
        *(__half2*)&Ol[ob0 + col] = l01;
        *(__half2*)&Oh[ob1 + col] = h23;
        *(__half2*)&Ol[ob1 + col] = l23;
    }
}

// ======================= launch ==============================================
extern "C" void kernel_launch(void* const* d_in, const int* in_sizes, int n_in,
                              void* d_out, int out_size)
{
    (void)in_sizes; (void)n_in; (void)out_size;
    const float* hs = (const float*)d_in[0];
    const float* cs = (const float*)d_in[1];
    const float* sn = (const float*)d_in[2];
    const float* Wq = (const float*)d_in[4];
    const float* Wk = (const float*)d_in[5];
    const float* Wv = (const float*)d_in[6];
    const float* Wo = (const float*)d_in[7];
    float* out = (float*)d_out;

    __half *hsh, *hsl, *wqh, *wql, *wkh, *wkl, *wvh, *wvl, *woh, *wol, *oh, *ol;
    __half *qh, *ql, *kh, *kl, *vh, *vl;
    cudaGetSymbolAddress((void**)&hsh, g_hs_h); cudaGetSymbolAddress((void**)&hsl, g_hs_l);
    cudaGetSymbolAddress((void**)&wqh, g_wq_h); cudaGetSymbolAddress((void**)&wql, g_wq_l);
    cudaGetSymbolAddress((void**)&wkh, g_wk_h); cudaGetSymbolAddress((void**)&wkl, g_wk_l);
    cudaGetSymbolAddress((void**)&wvh, g_wv_h); cudaGetSymbolAddress((void**)&wvl, g_wv_l);
    cudaGetSymbolAddress((void**)&woh, g_wo_h); cudaGetSymbolAddress((void**)&wol, g_wo_l);
    cudaGetSymbolAddress((void**)&oh,  g_o_h);  cudaGetSymbolAddress((void**)&ol,  g_o_l);
    cudaGetSymbolAddress((void**)&qh,  g_qh);   cudaGetSymbolAddress((void**)&ql,  g_ql);
    cudaGetSymbolAddress((void**)&kh,  g_kh);   cudaGetSymbolAddress((void**)&kl,  g_kl);
    cudaGetSymbolAddress((void**)&vh,  g_vh);   cudaGetSymbolAddress((void**)&vl,  g_vl);

    const int n_big = 4096 * 4096 / 4, n_sm = 1024 * 4096 / 4;
    split_hilo<<<(n_big + 255) / 256, 256>>>(hs, hsh, hsl, n_big);
    split_hilo<<<(n_big + 255) / 256, 256>>>(Wq, wqh, wql, n_big);
    split_hilo<<<(n_sm + 255) / 256, 256>>>(Wk, wkh, wkl, n_sm);
    split_hilo<<<(n_sm + 255) / 256, 256>>>(Wv, wvh, wvl, n_sm);
    split_hilo<<<(n_big + 255) / 256, 256>>>(Wo, woh, wol, n_big);

    cudaFuncSetAttribute(gemm3_h16<0>,
                         cudaFuncAttributeMaxDynamicSharedMemorySize, GSMEM_BYTES);
    cudaFuncSetAttribute(gemm3_h16<2>,
                         cudaFuncAttributeMaxDynamicSharedMemorySize, GSMEM_BYTES);

    // fused QKV projection + coalesced RoPE epilogue
    gemm3_h16<2><<<dim3(48, 16), 256, GSMEM_BYTES>>>(
        hsh, hsl, wqh, wql, wkh, wkl, wvh, wvl, cs, sn,
        nullptr, 4096, 0, qh, ql, kh, kl, vh, vl);

    cudaFuncSetAttribute(flash16,
                         cudaFuncAttributeMaxDynamicSharedMemorySize, FSMEM_BYTES);
    flash16<<<dim3(S_ / 128, NH_, B_), 256, FSMEM_BYTES>>>(
        qh, ql, kh, kl, vh, vl, oh, ol);

    // output projection: fp32 flat out
    gemm3_h16<0><<<dim3(32, 16), 256, GSMEM_BYTES>>>(
        oh, ol, woh, wol, nullptr, nullptr, nullptr, nullptr, nullptr, nullptr,
        out, 4096, 4096, nullptr, nullptr, nullptr, nullptr, nullptr, nullptr);
}